// round 13
// baseline (speedup 1.0000x reference)
#include <cuda_runtime.h>
#include <cuda_bf16.h>
#include <cuda_fp16.h>
#include <cstdint>

#define HIDDEN   2048
#define NHEADS   16
#define HEAD_DIM 128
#define BATCH    4
#define SEQ      2048
#define TOKENS   (BATCH * SEQ)     /* 8192 */
#define QKV_N    (3 * HIDDEN)      /* 6144 */
#define BH       (BATCH * NHEADS)  /* 64   */
#define SOFTMAX_SCALE 0.08838834764831845f
#define LOG2E 1.4426950408889634f

// ---------------------------------------------------------------------------
// Scratch (device globals)
// ---------------------------------------------------------------------------
__device__ float g_qkv[(size_t)TOKENS * QKV_N];
__device__ __nv_bfloat16 g_hh [(size_t)TOKENS * HIDDEN];
__device__ __nv_bfloat16 g_hl [(size_t)TOKENS * HIDDEN];
__device__ __nv_bfloat16 g_wqh[(size_t)QKV_N * HIDDEN];
__device__ __nv_bfloat16 g_wql[(size_t)QKV_N * HIDDEN];
__device__ __nv_bfloat16 g_wdh[(size_t)HIDDEN * HIDDEN];
__device__ __nv_bfloat16 g_wdl[(size_t)HIDDEN * HIDDEN];
__device__ __nv_bfloat16 g_ath[(size_t)TOKENS * HIDDEN];
__device__ __nv_bfloat16 g_atl[(size_t)TOKENS * HIDDEN];
__device__ __nv_bfloat16 g_qh[(size_t)BH * SEQ * HEAD_DIM];
__device__ __nv_bfloat16 g_ql[(size_t)BH * SEQ * HEAD_DIM];
__device__ __nv_bfloat16 g_kh[(size_t)BH * SEQ * HEAD_DIM];
__device__ __nv_bfloat16 g_kl[(size_t)BH * SEQ * HEAD_DIM];
__device__ __half g_vh[(size_t)BH * HEAD_DIM * SEQ];       // [bh][d][s]

// ---------------------------------------------------------------------------
// helpers
// ---------------------------------------------------------------------------
__device__ __forceinline__ uint32_t smem_u32(const void* p) {
    uint32_t a;
    asm("{ .reg .u64 t; cvta.to.shared.u64 t, %1; cvt.u32.u64 %0, t; }"
        : "=r"(a) : "l"(p));
    return a;
}
#define CVT_BF2(d, up, lo) \
    asm("cvt.rn.bf16x2.f32 %0, %1, %2;" : "=r"(d) : "f"(up), "f"(lo))
#define PACK_F16(d, up, lo) \
    asm("cvt.rn.f16x2.f32 %0, %1, %2;" : "=r"(d) : "f"(up), "f"(lo))

__device__ __forceinline__ float fast_exp2(float x) {
    float y;
    asm("ex2.approx.ftz.f32 %0, %1;" : "=f"(y) : "f"(x));
    return y;
}

#define LDSM4(r, addr) \
    asm volatile("ldmatrix.sync.aligned.m8n8.x4.shared.b16 {%0,%1,%2,%3}, [%4];" \
        : "=r"((r)[0]), "=r"((r)[1]), "=r"((r)[2]), "=r"((r)[3]) : "r"(addr))

#define MMA_BF16(cr, a, b0, b1) \
    asm volatile("mma.sync.aligned.m16n8k16.row.col.f32.bf16.bf16.f32 " \
        "{%0,%1,%2,%3}, {%4,%5,%6,%7}, {%8,%9}, {%0,%1,%2,%3};" \
        : "+f"((cr)[0]), "+f"((cr)[1]), "+f"((cr)[2]), "+f"((cr)[3]) \
        : "r"((a)[0]), "r"((a)[1]), "r"((a)[2]), "r"((a)[3]), "r"(b0), "r"(b1))

#define MMA_F16(cr, a, b0, b1) \
    asm volatile("mma.sync.aligned.m16n8k16.row.col.f32.f16.f16.f32 " \
        "{%0,%1,%2,%3}, {%4,%5,%6,%7}, {%8,%9}, {%0,%1,%2,%3};" \
        : "+f"((cr)[0]), "+f"((cr)[1]), "+f"((cr)[2]), "+f"((cr)[3]) \
        : "r"((a)[0]), "r"((a)[1]), "r"((a)[2]), "r"((a)[3]), "r"(b0), "r"(b1))

#define CP16(dst, src) \
    asm volatile("cp.async.ca.shared.global [%0], [%1], 16;" \
                 :: "r"(dst), "l"(src) : "memory")
#define CP_COMMIT() asm volatile("cp.async.commit_group;" ::: "memory")
#define CP_WAIT(n)  asm volatile("cp.async.wait_group %0;" :: "n"(n) : "memory")

__device__ __forceinline__ void split_sts(char* hip, char* lop, float4 v) {
    uint32_t h0 = __byte_perm(__float_as_uint(v.x), __float_as_uint(v.y), 0x7632);
    uint32_t h1 = __byte_perm(__float_as_uint(v.z), __float_as_uint(v.w), 0x7632);
    float lx = v.x - __uint_as_float(__float_as_uint(v.x) & 0xffff0000u);
    float ly = v.y - __uint_as_float(__float_as_uint(v.y) & 0xffff0000u);
    float lz = v.z - __uint_as_float(__float_as_uint(v.z) & 0xffff0000u);
    float lw = v.w - __uint_as_float(__float_as_uint(v.w) & 0xffff0000u);
    uint32_t l0, l1;
    CVT_BF2(l0, ly, lx);
    CVT_BF2(l1, lw, lz);
    *(uint2*)hip = make_uint2(h0, h1);
    *(uint2*)lop = make_uint2(l0, l1);
}

// ---------------------------------------------------------------------------
// Elementwise fp32 -> bf16 hi/lo split
// ---------------------------------------------------------------------------
__global__ void __launch_bounds__(256) split_f32(
    const float4* __restrict__ src, uint2* __restrict__ hi,
    uint2* __restrict__ lo, int n4)
{
    int i = blockIdx.x * 256 + threadIdx.x;
    if (i >= n4) return;
    float4 v = src[i];
    uint32_t h0 = __byte_perm(__float_as_uint(v.x), __float_as_uint(v.y), 0x7632);
    uint32_t h1 = __byte_perm(__float_as_uint(v.z), __float_as_uint(v.w), 0x7632);
    float lx = v.x - __uint_as_float(__float_as_uint(v.x) & 0xffff0000u);
    float ly = v.y - __uint_as_float(__float_as_uint(v.y) & 0xffff0000u);
    float lz = v.z - __uint_as_float(__float_as_uint(v.z) & 0xffff0000u);
    float lw = v.w - __uint_as_float(__float_as_uint(v.w) & 0xffff0000u);
    uint32_t l0, l1;
    CVT_BF2(l0, ly, lx);
    CVT_BF2(l1, lw, lz);
    hi[i] = make_uint2(h0, h1);
    lo[i] = make_uint2(l0, l1);
}

// ---------------------------------------------------------------------------
// Pre-split bf16x3 NT GEMM + bias. 3-stage cp.async pipeline, single sync/iter.
// ---------------------------------------------------------------------------
#define GROWB   80
#define GMAT    (128 * GROWB)
#define GSTAGE  (4 * GMAT)                 /* 40960 */
#define GSMEM   (3 * GSTAGE)               /* 122880 */

__global__ void __launch_bounds__(256, 1) gemm_bf16p(
    const __nv_bfloat16* __restrict__ Ah, const __nv_bfloat16* __restrict__ Al,
    const __nv_bfloat16* __restrict__ Bh, const __nv_bfloat16* __restrict__ Bl,
    const float* __restrict__ bias, float* __restrict__ C,
    int M, int N, int K)
{
    extern __shared__ char smem[];
    const uint32_t sbase = smem_u32(smem);

    const int tid  = threadIdx.x;
    const int wid  = tid >> 5;
    const int lane = tid & 31;
    const int bm = blockIdx.y << 7;
    const int bn = blockIdx.x << 7;

    const int m0 = (wid & 3) << 5;
    const int n0 = (wid >> 2) << 6;

    float c[2][8][4];
#pragma unroll
    for (int mt = 0; mt < 2; ++mt)
#pragma unroll
        for (int nt = 0; nt < 8; ++nt)
#pragma unroll
            for (int q = 0; q < 4; ++q) c[mt][nt][q] = 0.f;

    const int a_row = lane & 15;
    const int a_col = ((lane >> 4) & 1) << 3;
    const int b_mat = lane >> 3;
    const int b_nrow = (lane & 7) + ((b_mat & 1) << 3);
    const int b_kcol = (b_mat >> 1) << 3;

    const int lrow = tid >> 1;
    const int lseg = (tid & 1) << 1;
    const __nv_bfloat16* Ahg = Ah + (size_t)(bm + lrow) * K + lseg * 8;
    const __nv_bfloat16* Alg = Al + (size_t)(bm + lrow) * K + lseg * 8;
    const __nv_bfloat16* Bhg = Bh + (size_t)(bn + lrow) * K + lseg * 8;
    const __nv_bfloat16* Blg = Bl + (size_t)(bn + lrow) * K + lseg * 8;
    const uint32_t sto = (uint32_t)(lrow * GROWB + lseg * 16);

    const int KT = K >> 5;

    auto issue_stage = [&](int it, int st) {
        const uint32_t s = sbase + st * GSTAGE + sto;
        const size_t go = (size_t)it * 32;
        CP16(s,            Ahg + go);  CP16(s + 16,            Ahg + go + 8);
        CP16(s + GMAT,     Alg + go);  CP16(s + GMAT + 16,     Alg + go + 8);
        CP16(s + 2 * GMAT, Bhg + go);  CP16(s + 2 * GMAT + 16, Bhg + go + 8);
        CP16(s + 3 * GMAT, Blg + go);  CP16(s + 3 * GMAT + 16, Blg + go + 8);
        CP_COMMIT();
    };

    // prologue: stages 0, 1
    issue_stage(0, 0);
    if (KT > 1) issue_stage(1, 1);

    int st = 0;
    for (int it = 0; it < KT; ++it) {
        if (it + 1 < KT) { CP_WAIT(1); } else { CP_WAIT(0); }
        __syncthreads();

        // prefetch stage it+2 (buffer read at it-1; top barrier makes it free)
        if (it + 2 < KT) issue_stage(it + 2, (st + 2) % 3);

        const uint32_t sA  = sbase + st * GSTAGE;
        const uint32_t sAl = sA + GMAT;
        const uint32_t sB  = sA + 2 * GMAT;
        const uint32_t sBl = sA + 3 * GMAT;

#pragma unroll
        for (int ks = 0; ks < 2; ++ks) {
            const int kb = ks << 4;
            uint32_t ah[2][4], al[2][4], bh[4][4], bl[4][4];
            const uint32_t aoff = (uint32_t)(a_row * GROWB + (kb + a_col) * 2);
            const uint32_t boff = (uint32_t)(b_nrow * GROWB + (kb + b_kcol) * 2);
#pragma unroll
            for (int mt = 0; mt < 2; ++mt) {
                const uint32_t mo = (uint32_t)((m0 + mt * 16) * GROWB);
                LDSM4(ah[mt], sA  + mo + aoff);
                LDSM4(al[mt], sAl + mo + aoff);
            }
#pragma unroll
            for (int nq = 0; nq < 4; ++nq) {
                const uint32_t no = (uint32_t)((n0 + nq * 16) * GROWB);
                LDSM4(bh[nq], sB  + no + boff);
                LDSM4(bl[nq], sBl + no + boff);
            }
#pragma unroll
            for (int mt = 0; mt < 2; ++mt)
#pragma unroll
                for (int nt = 0; nt < 8; ++nt) {
                    const int nq = nt >> 1, sel = nt & 1;
                    MMA_BF16(c[mt][nt], ah[mt], bh[nq][sel], bh[nq][sel + 2]);
                    MMA_BF16(c[mt][nt], ah[mt], bl[nq][sel], bl[nq][sel + 2]);
                    MMA_BF16(c[mt][nt], al[mt], bh[nq][sel], bh[nq][sel + 2]);
                }
        }
        st = (st + 1) % 3;
    }

    const int grp = lane >> 2, tig = lane & 3;
#pragma unroll
    for (int nt = 0; nt < 8; ++nt) {
        const int col = bn + n0 + nt * 8 + tig * 2;
        const float2 bv = *(const float2*)&bias[col];
#pragma unroll
        for (int mt = 0; mt < 2; ++mt) {
            const int row = bm + m0 + mt * 16 + grp;
            float2 v0 = make_float2(c[mt][nt][0] + bv.x, c[mt][nt][1] + bv.y);
            float2 v1 = make_float2(c[mt][nt][2] + bv.x, c[mt][nt][3] + bv.y);
            *(float2*)&C[(size_t)row * N + col]       = v0;
            *(float2*)&C[(size_t)(row + 8) * N + col] = v1;
        }
    }
}

// ---------------------------------------------------------------------------
// Pre-pass: Q (scaled) and K -> bf16 hi/lo, layout [bh][s][d]
// ---------------------------------------------------------------------------
__global__ void __launch_bounds__(256) convert_qk(
    const float* __restrict__ qkv,
    __nv_bfloat16* __restrict__ qh, __nv_bfloat16* __restrict__ ql,
    __nv_bfloat16* __restrict__ kh, __nv_bfloat16* __restrict__ kl)
{
    const int gw   = blockIdx.x * 8 + (threadIdx.x >> 5);
    const int lane = threadIdx.x & 31;
    const int bh = gw >> 11;
    const int s  = gw & 2047;
    const int b  = bh >> 4;
    const int h  = bh & 15;

    const float* src = qkv + ((size_t)(b * SEQ + s)) * QKV_N + h * HEAD_DIM + lane * 4;
    float4 q = *(const float4*)src;
    float4 k = *(const float4*)(src + HIDDEN);
    q.x *= SOFTMAX_SCALE; q.y *= SOFTMAX_SCALE;
    q.z *= SOFTMAX_SCALE; q.w *= SOFTMAX_SCALE;

    const size_t dst = ((size_t)gw) * HEAD_DIM + lane * 4;
    split_sts((char*)(qh + dst), (char*)(ql + dst), q);
    split_sts((char*)(kh + dst), (char*)(kl + dst), k);
}

// ---------------------------------------------------------------------------
// Pre-pass: V -> fp16 (hi only), transposed to [bh][d][s]
// ---------------------------------------------------------------------------
__global__ void __launch_bounds__(256) convert_v(
    const float* __restrict__ qkv, __half* __restrict__ vh)
{
    __shared__ float t[32][33];

    const int s0 = blockIdx.x << 5;
    const int d0 = blockIdx.y << 5;
    const int bh = blockIdx.z;
    const int b  = bh >> 4;
    const int h  = bh & 15;

    const int col  = threadIdx.x & 31;
    const int rowb = threadIdx.x >> 5;

    const size_t inbase = ((size_t)(b * SEQ + s0)) * QKV_N + 2 * HIDDEN + h * HEAD_DIM + d0;
#pragma unroll
    for (int r = rowb; r < 32; r += 8)
        t[r][col] = qkv[inbase + (size_t)r * QKV_N + col];
    __syncthreads();

    const size_t outbase = ((size_t)bh * HEAD_DIM + d0) * SEQ + s0;
#pragma unroll
    for (int r = rowb; r < 32; r += 8)
        vh[outbase + (size_t)r * SEQ + col] = __float2half_rn(t[col][r]);
}

// ---------------------------------------------------------------------------
// Flash attention on tensor cores. R12 layout + 2-stage cp.async K/V pipeline.
// q-tile 128, key-tile 64, 8 warps. S: bf16x3. PV: fp16 hi.
// ---------------------------------------------------------------------------
#define QSTR 272
#define VSTR 144
#define SQH 0
#define SQL (SQH + 128 * QSTR)            /* 34816 */
#define SSTG (SQL + 128 * QSTR)           /* 69632: stage area */
#define AKH  0                            /* in-stage offsets */
#define AKL  (64 * QSTR)                  /* 17408 */
#define AVH  (2 * 64 * QSTR)              /* 34816 */
#define ASTAGE (2 * 64 * QSTR + 128 * VSTR)   /* 53248 */
#define ATTN_SMEM (SSTG + 2 * ASTAGE)     /* 176128 */

__global__ void __launch_bounds__(256, 1) attn_mma(
    const __nv_bfloat16* __restrict__ qh, const __nv_bfloat16* __restrict__ ql,
    const __nv_bfloat16* __restrict__ kh, const __nv_bfloat16* __restrict__ kl,
    const __half* __restrict__ vh,
    __nv_bfloat16* __restrict__ oh, __nv_bfloat16* __restrict__ ol)
{
    extern __shared__ char sm[];
    const uint32_t sbase = smem_u32(sm);

    const int iq = (int)gridDim.x - 1 - (int)blockIdx.x;   // heavy tiles first
    const int bh = blockIdx.y;
    const int b  = bh >> 4;
    const int h  = bh & 15;
    const int tid  = threadIdx.x;
    const int wid  = tid >> 5;
    const int lane = tid & 31;
    const int q0 = iq << 7;
    const int m0 = wid << 4;

    const int nkt = 2 * (iq + 1);

    // stage loader: key-tile jt -> stage st (cp.async, 12 x 16B per thread)
    auto load_stage = [&](int jt, int stg) {
        const int kt0 = jt << 6;
        const __nv_bfloat16* khg = kh + ((size_t)bh * SEQ + kt0) * HEAD_DIM;
        const __nv_bfloat16* klg = kl + ((size_t)bh * SEQ + kt0) * HEAD_DIM;
        const uint32_t sb = sbase + SSTG + stg * ASTAGE;
#pragma unroll
        for (int p = 0; p < 4; ++p) {
            const int i = tid + (p << 8);
            const int row = i >> 4, seg = i & 15;
            const uint32_t dst = sb + row * QSTR + seg * 16;
            CP16(dst,       khg + row * HEAD_DIM + seg * 8);
            CP16(dst + AKL, klg + row * HEAD_DIM + seg * 8);
        }
#pragma unroll
        for (int p = 0; p < 4; ++p) {
            const int i = tid + (p << 8);
            const int d = i >> 3, seg = i & 7;
            CP16(sb + AVH + d * VSTR + seg * 16,
                 vh + ((size_t)bh * HEAD_DIM + d) * SEQ + kt0 + seg * 8);
        }
        CP_COMMIT();
    };

    // Q tile (plain loads; covered by first barrier)
    {
        const uint4* qhg = (const uint4*)(qh + ((size_t)bh * SEQ + q0) * HEAD_DIM);
        const uint4* qlg = (const uint4*)(ql + ((size_t)bh * SEQ + q0) * HEAD_DIM);
#pragma unroll
        for (int i = tid; i < 2048; i += 256) {
            const int row = i >> 4, seg = i & 15;
            *(uint4*)(sm + SQH + row * QSTR + seg * 16) = qhg[row * 16 + seg];
            *(uint4*)(sm + SQL + row * QSTR + seg * 16) = qlg[row * 16 + seg];
        }
    }

    load_stage(0, 0);

    float co[16][4];
#pragma unroll
    for (int t = 0; t < 16; ++t)
#pragma unroll
        for (int q = 0; q < 4; ++q) co[t][q] = 0.f;
    float mr0 = -1e30f, mr1 = -1e30f, lr0 = 0.f, lr1 = 0.f;

    const int a_row = lane & 15;
    const int a_col = ((lane >> 4) & 1) << 3;
    const int b_mat = lane >> 3;
    const int b_nrow = (lane & 7) + ((b_mat & 1) << 3);
    const int b_kcol = (b_mat >> 1) << 3;

    for (int jt = 0; jt < nkt; ++jt) {
        // prefetch jt+1 into the other stage (read at jt-1; freed by its end-sync)
        if (jt + 1 < nkt) {
            load_stage(jt + 1, (jt + 1) & 1);
            CP_WAIT(1);
        } else {
            CP_WAIT(0);
        }
        __syncthreads();

        const uint32_t sS = sbase + SSTG + (jt & 1) * ASTAGE;
        const uint32_t sK  = sS;
        const uint32_t sKl = sS + AKL;
        const uint32_t sV  = sS + AVH;
        const int kt0 = jt << 6;

        float cs[8][4];
#pragma unroll
        for (int t = 0; t < 8; ++t)
#pragma unroll
            for (int q = 0; q < 4; ++q) cs[t][q] = 0.f;

#pragma unroll
        for (int ks = 0; ks < 8; ++ks) {
            const int kb = ks << 4;
            uint32_t ah[4], al[4], bhf[4][4], blf[4][4];
            const uint32_t aoff = (uint32_t)((m0 + a_row) * QSTR + (kb + a_col) * 2);
            LDSM4(ah, sbase + SQH + aoff);
            LDSM4(al, sbase + SQL + aoff);
            const uint32_t boff = (uint32_t)(b_nrow * QSTR + (kb + b_kcol) * 2);
#pragma unroll
            for (int nq = 0; nq < 4; ++nq) {
                const uint32_t no = (uint32_t)(nq * 16 * QSTR);
                LDSM4(bhf[nq], sK  + no + boff);
                LDSM4(blf[nq], sKl + no + boff);
            }
#pragma unroll
            for (int nt = 0; nt < 8; ++nt) {
                const int nq = nt >> 1, sel = nt & 1;
                MMA_BF16(cs[nt], ah, bhf[nq][sel], bhf[nq][sel + 2]);
                MMA_BF16(cs[nt], ah, blf[nq][sel], blf[nq][sel + 2]);
                MMA_BF16(cs[nt], al, bhf[nq][sel], bhf[nq][sel + 2]);
            }
        }

        if (jt >= 2 * iq) {
            const int rg0 = q0 + m0 + (lane >> 2);
            const int rg1 = rg0 + 8;
            const int cb  = kt0 + ((lane & 3) << 1);
#pragma unroll
            for (int nt = 0; nt < 8; ++nt) {
                const int c0 = cb + nt * 8;
                if (c0     > rg0) cs[nt][0] = -1e30f;
                if (c0 + 1 > rg0) cs[nt][1] = -1e30f;
                if (c0     > rg1) cs[nt][2] = -1e30f;
                if (c0 + 1 > rg1) cs[nt][3] = -1e30f;
            }
        }

        float mx0 = cs[0][0], mx1 = cs[0][2];
#pragma unroll
        for (int nt = 0; nt < 8; ++nt) {
            mx0 = fmaxf(mx0, fmaxf(cs[nt][0], cs[nt][1]));
            mx1 = fmaxf(mx1, fmaxf(cs[nt][2], cs[nt][3]));
        }
        mx0 = fmaxf(mx0, __shfl_xor_sync(0xffffffffu, mx0, 1));
        mx0 = fmaxf(mx0, __shfl_xor_sync(0xffffffffu, mx0, 2));
        mx1 = fmaxf(mx1, __shfl_xor_sync(0xffffffffu, mx1, 1));
        mx1 = fmaxf(mx1, __shfl_xor_sync(0xffffffffu, mx1, 2));

        const float mn0 = fmaxf(mr0, mx0);
        const float mn1 = fmaxf(mr1, mx1);
        const float corr0 = fast_exp2((mr0 - mn0) * LOG2E);
        const float corr1 = fast_exp2((mr1 - mn1) * LOG2E);
        mr0 = mn0; mr1 = mn1;

        float rs0 = 0.f, rs1 = 0.f;
#pragma unroll
        for (int nt = 0; nt < 8; ++nt) {
            float p0 = fast_exp2((cs[nt][0] - mn0) * LOG2E);
            float p1 = fast_exp2((cs[nt][1] - mn0) * LOG2E);
            float p2 = fast_exp2((cs[nt][2] - mn1) * LOG2E);
            float p3 = fast_exp2((cs[nt][3] - mn1) * LOG2E);
            cs[nt][0] = p0; cs[nt][1] = p1; cs[nt][2] = p2; cs[nt][3] = p3;
            rs0 += p0 + p1; rs1 += p2 + p3;
        }
        rs0 += __shfl_xor_sync(0xffffffffu, rs0, 1);
        rs0 += __shfl_xor_sync(0xffffffffu, rs0, 2);
        rs1 += __shfl_xor_sync(0xffffffffu, rs1, 1);
        rs1 += __shfl_xor_sync(0xffffffffu, rs1, 2);
        lr0 = lr0 * corr0 + rs0;
        lr1 = lr1 * corr1 + rs1;
#pragma unroll
        for (int t = 0; t < 16; ++t) {
            co[t][0] *= corr0; co[t][1] *= corr0;
            co[t][2] *= corr1; co[t][3] *= corr1;
        }

        uint32_t pa[4][4];
#pragma unroll
        for (int t = 0; t < 4; ++t) {
            PACK_F16(pa[t][0], cs[2 * t][1],     cs[2 * t][0]);
            PACK_F16(pa[t][1], cs[2 * t][3],     cs[2 * t][2]);
            PACK_F16(pa[t][2], cs[2 * t + 1][1], cs[2 * t + 1][0]);
            PACK_F16(pa[t][3], cs[2 * t + 1][3], cs[2 * t + 1][2]);
        }

#pragma unroll
        for (int ks = 0; ks < 4; ++ks) {
            const uint32_t voff = (uint32_t)(b_nrow * VSTR + ((ks << 4) + b_kcol) * 2);
#pragma unroll
            for (int nq = 0; nq < 8; ++nq) {
                uint32_t vhf[4];
                const uint32_t no = (uint32_t)(nq * 16 * VSTR);
                LDSM4(vhf, sV + no + voff);
                MMA_F16(co[nq * 2],     pa[ks], vhf[0], vhf[2]);
                MMA_F16(co[nq * 2 + 1], pa[ks], vhf[1], vhf[3]);
            }
        }
        __syncthreads();   // stage (jt&1) free for prefetch at jt+1
    }

    // ---- epilogue: normalize, split to bf16 hi/lo ----
    const float inv0 = 1.f / lr0;
    const float inv1 = 1.f / lr1;
    const size_t row0 = (size_t)(b * SEQ + q0 + m0 + (lane >> 2));
#pragma unroll
    for (int t = 0; t < 16; ++t) {
        const int col = h * HEAD_DIM + t * 8 + ((lane & 3) << 1);
        float a0 = co[t][0] * inv0, a1 = co[t][1] * inv0;
        float b0v = co[t][2] * inv1, b1v = co[t][3] * inv1;
        uint32_t h0 = __byte_perm(__float_as_uint(a0), __float_as_uint(a1), 0x7632);
        uint32_t h1 = __byte_perm(__float_as_uint(b0v), __float_as_uint(b1v), 0x7632);
        float l0a = a0 - __uint_as_float(__float_as_uint(a0) & 0xffff0000u);
        float l1a = a1 - __uint_as_float(__float_as_uint(a1) & 0xffff0000u);
        float l0b = b0v - __uint_as_float(__float_as_uint(b0v) & 0xffff0000u);
        float l1b = b1v - __uint_as_float(__float_as_uint(b1v) & 0xffff0000u);
        uint32_t lo0, lo1;
        CVT_BF2(lo0, l1a, l0a);
        CVT_BF2(lo1, l1b, l0b);
        *(uint32_t*)&oh[row0 * HIDDEN + col]       = h0;
        *(uint32_t*)&ol[row0 * HIDDEN + col]       = lo0;
        *(uint32_t*)&oh[(row0 + 8) * HIDDEN + col] = h1;
        *(uint32_t*)&ol[(row0 + 8) * HIDDEN + col] = lo1;
    }
}

// ---------------------------------------------------------------------------
// Launch
// ---------------------------------------------------------------------------
extern "C" void kernel_launch(void* const* d_in, const int* in_sizes, int n_in,
                              void* d_out, int out_size)
{
    const float* hidden  = (const float*)d_in[0];
    const float* w_qkv   = (const float*)d_in[1];
    const float* b_qkv   = (const float*)d_in[2];
    const float* w_dense = (const float*)d_in[3];
    const float* b_dense = (const float*)d_in[4];
    float* out = (float*)d_out;

    float* qkv_p;
    __nv_bfloat16 *hh, *hl, *wqh, *wql, *wdh, *wdl, *ath, *atl;
    __nv_bfloat16 *qh_p, *ql_p, *kh_p, *kl_p;
    __half *vh_p;
    cudaGetSymbolAddress((void**)&qkv_p, g_qkv);
    cudaGetSymbolAddress((void**)&hh,  g_hh);
    cudaGetSymbolAddress((void**)&hl,  g_hl);
    cudaGetSymbolAddress((void**)&wqh, g_wqh);
    cudaGetSymbolAddress((void**)&wql, g_wql);
    cudaGetSymbolAddress((void**)&wdh, g_wdh);
    cudaGetSymbolAddress((void**)&wdl, g_wdl);
    cudaGetSymbolAddress((void**)&ath, g_ath);
    cudaGetSymbolAddress((void**)&atl, g_atl);
    cudaGetSymbolAddress((void**)&qh_p, g_qh);
    cudaGetSymbolAddress((void**)&ql_p, g_ql);
    cudaGetSymbolAddress((void**)&kh_p, g_kh);
    cudaGetSymbolAddress((void**)&kl_p, g_kl);
    cudaGetSymbolAddress((void**)&vh_p, g_vh);

    cudaFuncSetAttribute(gemm_bf16p,
                         cudaFuncAttributeMaxDynamicSharedMemorySize, GSMEM);
    cudaFuncSetAttribute(attn_mma,
                         cudaFuncAttributeMaxDynamicSharedMemorySize, ATTN_SMEM);

    dim3 blk(256);

    // 0) pre-split GEMM operands
    {
        int n4 = TOKENS * HIDDEN / 4;
        split_f32<<<(n4 + 255) / 256, blk>>>((const float4*)hidden,
                                             (uint2*)hh, (uint2*)hl, n4);
        n4 = QKV_N * HIDDEN / 4;
        split_f32<<<(n4 + 255) / 256, blk>>>((const float4*)w_qkv,
                                             (uint2*)wqh, (uint2*)wql, n4);
        n4 = HIDDEN * HIDDEN / 4;
        split_f32<<<(n4 + 255) / 256, blk>>>((const float4*)w_dense,
                                             (uint2*)wdh, (uint2*)wdl, n4);
    }

    // 1) QKV projection
    gemm_bf16p<<<dim3(QKV_N / 128, TOKENS / 128), blk, GSMEM>>>(
        hh, hl, wqh, wql, b_qkv, qkv_p, TOKENS, QKV_N, HIDDEN);

    // 2) Convert Q (scaled), K to bf16 hi/lo
    convert_qk<<<(BH * SEQ) / 8, blk>>>(qkv_p, qh_p, ql_p, kh_p, kl_p);

    // 3) Convert + transpose V to fp16 (hi only)
    convert_v<<<dim3(SEQ / 32, HEAD_DIM / 32, BH), blk>>>(qkv_p, vh_p);

    // 4) Tensor-core flash attention (bf16 hi/lo out)
    attn_mma<<<dim3(SEQ / 128, BH), blk, ATTN_SMEM>>>(
        qh_p, ql_p, kh_p, kl_p, vh_p, ath, atl);

    // 5) Dense projection
    gemm_bf16p<<<dim3(HIDDEN / 128, TOKENS / 128), blk, GSMEM>>>(
        ath, atl, wdh, wdl, b_dense, out, TOKENS, HIDDEN, HIDDEN);
}

// round 14
// speedup vs baseline: 1.0804x; 1.0804x over previous
#include <cuda_runtime.h>
#include <cuda_bf16.h>
#include <cuda_fp16.h>
#include <cstdint>

#define HIDDEN   2048
#define NHEADS   16
#define HEAD_DIM 128
#define BATCH    4
#define SEQ      2048
#define TOKENS   (BATCH * SEQ)     /* 8192 */
#define QKV_N    (3 * HIDDEN)      /* 6144 */
#define BH       (BATCH * NHEADS)  /* 64   */
#define SOFTMAX_SCALE 0.08838834764831845f
#define LOG2E 1.4426950408889634f

// ---------------------------------------------------------------------------
// Scratch (device globals)
// ---------------------------------------------------------------------------
__device__ float g_qkv[(size_t)TOKENS * QKV_N];
__device__ __nv_bfloat16 g_hh [(size_t)TOKENS * HIDDEN];
__device__ __nv_bfloat16 g_hl [(size_t)TOKENS * HIDDEN];
__device__ __nv_bfloat16 g_wqh[(size_t)QKV_N * HIDDEN];
__device__ __nv_bfloat16 g_wql[(size_t)QKV_N * HIDDEN];
__device__ __nv_bfloat16 g_wdh[(size_t)HIDDEN * HIDDEN];
__device__ __nv_bfloat16 g_wdl[(size_t)HIDDEN * HIDDEN];
__device__ __nv_bfloat16 g_ath[(size_t)TOKENS * HIDDEN];
__device__ __nv_bfloat16 g_atl[(size_t)TOKENS * HIDDEN];
__device__ __nv_bfloat16 g_qh[(size_t)BH * SEQ * HEAD_DIM];
__device__ __nv_bfloat16 g_ql[(size_t)BH * SEQ * HEAD_DIM];
__device__ __nv_bfloat16 g_kh[(size_t)BH * SEQ * HEAD_DIM];
__device__ __nv_bfloat16 g_kl[(size_t)BH * SEQ * HEAD_DIM];
__device__ __half g_vh[(size_t)BH * HEAD_DIM * SEQ];       // [bh][d][s]

// ---------------------------------------------------------------------------
// helpers
// ---------------------------------------------------------------------------
__device__ __forceinline__ uint32_t smem_u32(const void* p) {
    uint32_t a;
    asm("{ .reg .u64 t; cvta.to.shared.u64 t, %1; cvt.u32.u64 %0, t; }"
        : "=r"(a) : "l"(p));
    return a;
}
#define CVT_BF2(d, up, lo) \
    asm("cvt.rn.bf16x2.f32 %0, %1, %2;" : "=r"(d) : "f"(up), "f"(lo))
#define PACK_F16(d, up, lo) \
    asm("cvt.rn.f16x2.f32 %0, %1, %2;" : "=r"(d) : "f"(up), "f"(lo))

__device__ __forceinline__ float fast_exp2(float x) {
    float y;
    asm("ex2.approx.ftz.f32 %0, %1;" : "=f"(y) : "f"(x));
    return y;
}

#define LDSM4(r, addr) \
    asm volatile("ldmatrix.sync.aligned.m8n8.x4.shared.b16 {%0,%1,%2,%3}, [%4];" \
        : "=r"((r)[0]), "=r"((r)[1]), "=r"((r)[2]), "=r"((r)[3]) : "r"(addr))

#define MMA_BF16(cr, a, b0, b1) \
    asm volatile("mma.sync.aligned.m16n8k16.row.col.f32.bf16.bf16.f32 " \
        "{%0,%1,%2,%3}, {%4,%5,%6,%7}, {%8,%9}, {%0,%1,%2,%3};" \
        : "+f"((cr)[0]), "+f"((cr)[1]), "+f"((cr)[2]), "+f"((cr)[3]) \
        : "r"((a)[0]), "r"((a)[1]), "r"((a)[2]), "r"((a)[3]), "r"(b0), "r"(b1))

#define MMA_F16(cr, a, b0, b1) \
    asm volatile("mma.sync.aligned.m16n8k16.row.col.f32.f16.f16.f32 " \
        "{%0,%1,%2,%3}, {%4,%5,%6,%7}, {%8,%9}, {%0,%1,%2,%3};" \
        : "+f"((cr)[0]), "+f"((cr)[1]), "+f"((cr)[2]), "+f"((cr)[3]) \
        : "r"((a)[0]), "r"((a)[1]), "r"((a)[2]), "r"((a)[3]), "r"(b0), "r"(b1))

#define CP16(dst, src) \
    asm volatile("cp.async.ca.shared.global [%0], [%1], 16;" \
                 :: "r"(dst), "l"(src) : "memory")
#define CP_COMMIT() asm volatile("cp.async.commit_group;" ::: "memory")
#define CP_WAIT(n)  asm volatile("cp.async.wait_group %0;" :: "n"(n) : "memory")

__device__ __forceinline__ void split_sts(char* hip, char* lop, float4 v) {
    uint32_t h0 = __byte_perm(__float_as_uint(v.x), __float_as_uint(v.y), 0x7632);
    uint32_t h1 = __byte_perm(__float_as_uint(v.z), __float_as_uint(v.w), 0x7632);
    float lx = v.x - __uint_as_float(__float_as_uint(v.x) & 0xffff0000u);
    float ly = v.y - __uint_as_float(__float_as_uint(v.y) & 0xffff0000u);
    float lz = v.z - __uint_as_float(__float_as_uint(v.z) & 0xffff0000u);
    float lw = v.w - __uint_as_float(__float_as_uint(v.w) & 0xffff0000u);
    uint32_t l0, l1;
    CVT_BF2(l0, ly, lx);
    CVT_BF2(l1, lw, lz);
    *(uint2*)hip = make_uint2(h0, h1);
    *(uint2*)lop = make_uint2(l0, l1);
}

// ---------------------------------------------------------------------------
// Elementwise fp32 -> bf16 hi/lo split
// ---------------------------------------------------------------------------
__global__ void __launch_bounds__(256) split_f32(
    const float4* __restrict__ src, uint2* __restrict__ hi,
    uint2* __restrict__ lo, int n4)
{
    int i = blockIdx.x * 256 + threadIdx.x;
    if (i >= n4) return;
    float4 v = src[i];
    uint32_t h0 = __byte_perm(__float_as_uint(v.x), __float_as_uint(v.y), 0x7632);
    uint32_t h1 = __byte_perm(__float_as_uint(v.z), __float_as_uint(v.w), 0x7632);
    float lx = v.x - __uint_as_float(__float_as_uint(v.x) & 0xffff0000u);
    float ly = v.y - __uint_as_float(__float_as_uint(v.y) & 0xffff0000u);
    float lz = v.z - __uint_as_float(__float_as_uint(v.z) & 0xffff0000u);
    float lw = v.w - __uint_as_float(__float_as_uint(v.w) & 0xffff0000u);
    uint32_t l0, l1;
    CVT_BF2(l0, ly, lx);
    CVT_BF2(l1, lw, lz);
    hi[i] = make_uint2(h0, h1);
    lo[i] = make_uint2(l0, l1);
}

// ---------------------------------------------------------------------------
// Pre-split bf16x3 NT GEMM + bias via mma.sync + cp.async (exact R12 — 2-stage,
// 80KB smem, 2 CTAs/SM)
// ---------------------------------------------------------------------------
#define GROWB   80
#define GMAT    (128 * GROWB)
#define GSTAGE  (4 * GMAT)
#define GSMEM   (2 * GSTAGE)

__global__ void __launch_bounds__(256, 1) gemm_bf16p(
    const __nv_bfloat16* __restrict__ Ah, const __nv_bfloat16* __restrict__ Al,
    const __nv_bfloat16* __restrict__ Bh, const __nv_bfloat16* __restrict__ Bl,
    const float* __restrict__ bias, float* __restrict__ C,
    int M, int N, int K)
{
    extern __shared__ char smem[];
    const uint32_t sbase = smem_u32(smem);

    const int tid  = threadIdx.x;
    const int wid  = tid >> 5;
    const int lane = tid & 31;
    const int bm = blockIdx.y << 7;
    const int bn = blockIdx.x << 7;

    const int m0 = (wid & 3) << 5;
    const int n0 = (wid >> 2) << 6;

    float c[2][8][4];
#pragma unroll
    for (int mt = 0; mt < 2; ++mt)
#pragma unroll
        for (int nt = 0; nt < 8; ++nt)
#pragma unroll
            for (int q = 0; q < 4; ++q) c[mt][nt][q] = 0.f;

    const int a_row = lane & 15;
    const int a_col = ((lane >> 4) & 1) << 3;
    const int b_mat = lane >> 3;
    const int b_nrow = (lane & 7) + ((b_mat & 1) << 3);
    const int b_kcol = (b_mat >> 1) << 3;

    const int lrow = tid >> 1;
    const int lseg = (tid & 1) << 1;
    const __nv_bfloat16* Ahg = Ah + (size_t)(bm + lrow) * K + lseg * 8;
    const __nv_bfloat16* Alg = Al + (size_t)(bm + lrow) * K + lseg * 8;
    const __nv_bfloat16* Bhg = Bh + (size_t)(bn + lrow) * K + lseg * 8;
    const __nv_bfloat16* Blg = Bl + (size_t)(bn + lrow) * K + lseg * 8;
    const uint32_t sto = (uint32_t)(lrow * GROWB + lseg * 16);

    const int KT = K >> 5;

    {
        const uint32_t s0 = sbase + sto;
        CP16(s0,             Ahg);      CP16(s0 + 16,             Ahg + 8);
        CP16(s0 + GMAT,      Alg);      CP16(s0 + GMAT + 16,      Alg + 8);
        CP16(s0 + 2 * GMAT,  Bhg);      CP16(s0 + 2 * GMAT + 16,  Bhg + 8);
        CP16(s0 + 3 * GMAT,  Blg);      CP16(s0 + 3 * GMAT + 16,  Blg + 8);
        CP_COMMIT();
    }

    for (int it = 0; it < KT; ++it) {
        const int buf = it & 1;
        if (it + 1 < KT) {
            const uint32_t s1 = sbase + ((it + 1) & 1) * GSTAGE + sto;
            const size_t go = (size_t)(it + 1) * 32;
            CP16(s1,            Ahg + go);  CP16(s1 + 16,            Ahg + go + 8);
            CP16(s1 + GMAT,     Alg + go);  CP16(s1 + GMAT + 16,     Alg + go + 8);
            CP16(s1 + 2 * GMAT, Bhg + go);  CP16(s1 + 2 * GMAT + 16, Bhg + go + 8);
            CP16(s1 + 3 * GMAT, Blg + go);  CP16(s1 + 3 * GMAT + 16, Blg + go + 8);
            CP_COMMIT();
            CP_WAIT(1);
        } else {
            CP_WAIT(0);
        }
        __syncthreads();

        const uint32_t sA  = sbase + buf * GSTAGE;
        const uint32_t sAl = sA + GMAT;
        const uint32_t sB  = sA + 2 * GMAT;
        const uint32_t sBl = sA + 3 * GMAT;

#pragma unroll
        for (int ks = 0; ks < 2; ++ks) {
            const int kb = ks << 4;
            uint32_t ah[2][4], al[2][4], bh[4][4], bl[4][4];
            const uint32_t aoff = (uint32_t)(a_row * GROWB + (kb + a_col) * 2);
            const uint32_t boff = (uint32_t)(b_nrow * GROWB + (kb + b_kcol) * 2);
#pragma unroll
            for (int mt = 0; mt < 2; ++mt) {
                const uint32_t mo = (uint32_t)((m0 + mt * 16) * GROWB);
                LDSM4(ah[mt], sA  + mo + aoff);
                LDSM4(al[mt], sAl + mo + aoff);
            }
#pragma unroll
            for (int nq = 0; nq < 4; ++nq) {
                const uint32_t no = (uint32_t)((n0 + nq * 16) * GROWB);
                LDSM4(bh[nq], sB  + no + boff);
                LDSM4(bl[nq], sBl + no + boff);
            }
#pragma unroll
            for (int mt = 0; mt < 2; ++mt)
#pragma unroll
                for (int nt = 0; nt < 8; ++nt) {
                    const int nq = nt >> 1, sel = nt & 1;
                    MMA_BF16(c[mt][nt], ah[mt], bh[nq][sel], bh[nq][sel + 2]);
                    MMA_BF16(c[mt][nt], ah[mt], bl[nq][sel], bl[nq][sel + 2]);
                    MMA_BF16(c[mt][nt], al[mt], bh[nq][sel], bh[nq][sel + 2]);
                }
        }
        __syncthreads();
    }

    const int grp = lane >> 2, tig = lane & 3;
#pragma unroll
    for (int nt = 0; nt < 8; ++nt) {
        const int col = bn + n0 + nt * 8 + tig * 2;
        const float2 bv = *(const float2*)&bias[col];
#pragma unroll
        for (int mt = 0; mt < 2; ++mt) {
            const int row = bm + m0 + mt * 16 + grp;
            float2 v0 = make_float2(c[mt][nt][0] + bv.x, c[mt][nt][1] + bv.y);
            float2 v1 = make_float2(c[mt][nt][2] + bv.x, c[mt][nt][3] + bv.y);
            *(float2*)&C[(size_t)row * N + col]       = v0;
            *(float2*)&C[(size_t)(row + 8) * N + col] = v1;
        }
    }
}

// ---------------------------------------------------------------------------
// Pre-pass: Q (scaled) and K -> bf16 hi/lo, layout [bh][s][d]
// ---------------------------------------------------------------------------
__global__ void __launch_bounds__(256) convert_qk(
    const float* __restrict__ qkv,
    __nv_bfloat16* __restrict__ qh, __nv_bfloat16* __restrict__ ql,
    __nv_bfloat16* __restrict__ kh, __nv_bfloat16* __restrict__ kl)
{
    const int gw   = blockIdx.x * 8 + (threadIdx.x >> 5);
    const int lane = threadIdx.x & 31;
    const int bh = gw >> 11;
    const int s  = gw & 2047;
    const int b  = bh >> 4;
    const int h  = bh & 15;

    const float* src = qkv + ((size_t)(b * SEQ + s)) * QKV_N + h * HEAD_DIM + lane * 4;
    float4 q = *(const float4*)src;
    float4 k = *(const float4*)(src + HIDDEN);
    q.x *= SOFTMAX_SCALE; q.y *= SOFTMAX_SCALE;
    q.z *= SOFTMAX_SCALE; q.w *= SOFTMAX_SCALE;

    const size_t dst = ((size_t)gw) * HEAD_DIM + lane * 4;
    split_sts((char*)(qh + dst), (char*)(ql + dst), q);
    split_sts((char*)(kh + dst), (char*)(kl + dst), k);
}

// ---------------------------------------------------------------------------
// Pre-pass: V -> fp16 (hi only), transposed to [bh][d][s]
// ---------------------------------------------------------------------------
__global__ void __launch_bounds__(256) convert_v(
    const float* __restrict__ qkv, __half* __restrict__ vh)
{
    __shared__ float t[32][33];

    const int s0 = blockIdx.x << 5;
    const int d0 = blockIdx.y << 5;
    const int bh = blockIdx.z;
    const int b  = bh >> 4;
    const int h  = bh & 15;

    const int col  = threadIdx.x & 31;
    const int rowb = threadIdx.x >> 5;

    const size_t inbase = ((size_t)(b * SEQ + s0)) * QKV_N + 2 * HIDDEN + h * HEAD_DIM + d0;
#pragma unroll
    for (int r = rowb; r < 32; r += 8)
        t[r][col] = qkv[inbase + (size_t)r * QKV_N + col];
    __syncthreads();

    const size_t outbase = ((size_t)bh * HEAD_DIM + d0) * SEQ + s0;
#pragma unroll
    for (int r = rowb; r < 32; r += 8)
        vh[outbase + (size_t)r * SEQ + col] = __float2half_rn(t[col][r]);
}

// ---------------------------------------------------------------------------
// Flash attention, tensor cores. Q fragments REGISTER-RESIDENT (loaded once),
// K/V double-buffered via cp.async. q-tile 128, key-tile 64, 8 warps.
// S: bf16x3. PV: fp16 hi.
// ---------------------------------------------------------------------------
#define QSTR 272
#define VSTR 144
#define AKL  (64 * QSTR)                  /* 17408 */
#define AVH  (2 * 64 * QSTR)              /* 34816 */
#define ASTAGE (2 * 64 * QSTR + 128 * VSTR)   /* 53248 */
#define ATTN_SMEM (2 * ASTAGE)            /* 106496 */

__global__ void __launch_bounds__(256, 1) attn_mma(
    const __nv_bfloat16* __restrict__ qh, const __nv_bfloat16* __restrict__ ql,
    const __nv_bfloat16* __restrict__ kh, const __nv_bfloat16* __restrict__ kl,
    const __half* __restrict__ vh,
    __nv_bfloat16* __restrict__ oh, __nv_bfloat16* __restrict__ ol)
{
    extern __shared__ char sm[];
    const uint32_t sbase = smem_u32(sm);

    const int iq = (int)gridDim.x - 1 - (int)blockIdx.x;   // heavy tiles first
    const int bh = blockIdx.y;
    const int b  = bh >> 4;
    const int h  = bh & 15;
    const int tid  = threadIdx.x;
    const int wid  = tid >> 5;
    const int lane = tid & 31;
    const int q0 = iq << 7;
    const int m0 = wid << 4;

    const int nkt = 2 * (iq + 1);

    const int a_row = lane & 15;
    const int a_col = ((lane >> 4) & 1) << 3;
    const int b_mat = lane >> 3;
    const int b_nrow = (lane & 7) + ((b_mat & 1) << 3);
    const int b_kcol = (b_mat >> 1) << 3;

    // ---- stage Q in smem once, ldmatrix to persistent registers ----
    uint32_t qfh[8][4], qfl[8][4];
    {
        const uint4* qhg = (const uint4*)(qh + ((size_t)bh * SEQ + q0) * HEAD_DIM);
        const uint4* qlg = (const uint4*)(ql + ((size_t)bh * SEQ + q0) * HEAD_DIM);
#pragma unroll
        for (int i = tid; i < 2048; i += 256) {
            const int row = i >> 4, seg = i & 15;
            *(uint4*)(sm + row * QSTR + seg * 16)         = qhg[row * 16 + seg];
            *(uint4*)(sm + 34816 + row * QSTR + seg * 16) = qlg[row * 16 + seg];
        }
        __syncthreads();
#pragma unroll
        for (int ks = 0; ks < 8; ++ks) {
            const uint32_t aoff =
                (uint32_t)((m0 + a_row) * QSTR + ((ks << 4) + a_col) * 2);
            LDSM4(qfh[ks], sbase + aoff);
            LDSM4(qfl[ks], sbase + 34816 + aoff);
        }
        __syncthreads();   // Q fully consumed; smem now free for K/V stages
    }

    // stage loader: key-tile jt -> stage stg (cp.async)
    auto load_stage = [&](int jt, int stg) {
        const int kt0 = jt << 6;
        const __nv_bfloat16* khg = kh + ((size_t)bh * SEQ + kt0) * HEAD_DIM;
        const __nv_bfloat16* klg = kl + ((size_t)bh * SEQ + kt0) * HEAD_DIM;
        const uint32_t sb = sbase + stg * ASTAGE;
#pragma unroll
        for (int p = 0; p < 4; ++p) {
            const int i = tid + (p << 8);
            const int row = i >> 4, seg = i & 15;
            const uint32_t dst = sb + row * QSTR + seg * 16;
            CP16(dst,       khg + row * HEAD_DIM + seg * 8);
            CP16(dst + AKL, klg + row * HEAD_DIM + seg * 8);
        }
#pragma unroll
        for (int p = 0; p < 4; ++p) {
            const int i = tid + (p << 8);
            const int d = i >> 3, seg = i & 7;
            CP16(sb + AVH + d * VSTR + seg * 16,
                 vh + ((size_t)bh * HEAD_DIM + d) * SEQ + kt0 + seg * 8);
        }
        CP_COMMIT();
    };

    load_stage(0, 0);

    float co[16][4];
#pragma unroll
    for (int t = 0; t < 16; ++t)
#pragma unroll
        for (int q = 0; q < 4; ++q) co[t][q] = 0.f;
    float mr0 = -1e30f, mr1 = -1e30f, lr0 = 0.f, lr1 = 0.f;

    for (int jt = 0; jt < nkt; ++jt) {
        // prefetch jt+1 into the other stage (read at jt-1; freed by its end-sync)
        if (jt + 1 < nkt) {
            load_stage(jt + 1, (jt + 1) & 1);
            CP_WAIT(1);
        } else {
            CP_WAIT(0);
        }
        __syncthreads();

        const uint32_t sS = sbase + (jt & 1) * ASTAGE;
        const uint32_t sK  = sS;
        const uint32_t sKl = sS + AKL;
        const uint32_t sV  = sS + AVH;
        const int kt0 = jt << 6;

        // ---- S = Q K^T (Q from registers) ----
        float cs[8][4];
#pragma unroll
        for (int t = 0; t < 8; ++t)
#pragma unroll
            for (int q = 0; q < 4; ++q) cs[t][q] = 0.f;

#pragma unroll
        for (int ks = 0; ks < 8; ++ks) {
            const int kb = ks << 4;
            uint32_t bhf[4][4], blf[4][4];
            const uint32_t boff = (uint32_t)(b_nrow * QSTR + (kb + b_kcol) * 2);
#pragma unroll
            for (int nq = 0; nq < 4; ++nq) {
                const uint32_t no = (uint32_t)(nq * 16 * QSTR);
                LDSM4(bhf[nq], sK  + no + boff);
                LDSM4(blf[nq], sKl + no + boff);
            }
#pragma unroll
            for (int nt = 0; nt < 8; ++nt) {
                const int nq = nt >> 1, sel = nt & 1;
                MMA_BF16(cs[nt], qfh[ks], bhf[nq][sel], bhf[nq][sel + 2]);
                MMA_BF16(cs[nt], qfh[ks], blf[nq][sel], blf[nq][sel + 2]);
                MMA_BF16(cs[nt], qfl[ks], bhf[nq][sel], bhf[nq][sel + 2]);
            }
        }

        if (jt >= 2 * iq) {
            const int rg0 = q0 + m0 + (lane >> 2);
            const int rg1 = rg0 + 8;
            const int cb  = kt0 + ((lane & 3) << 1);
#pragma unroll
            for (int nt = 0; nt < 8; ++nt) {
                const int c0 = cb + nt * 8;
                if (c0     > rg0) cs[nt][0] = -1e30f;
                if (c0 + 1 > rg0) cs[nt][1] = -1e30f;
                if (c0     > rg1) cs[nt][2] = -1e30f;
                if (c0 + 1 > rg1) cs[nt][3] = -1e30f;
            }
        }

        float mx0 = cs[0][0], mx1 = cs[0][2];
#pragma unroll
        for (int nt = 0; nt < 8; ++nt) {
            mx0 = fmaxf(mx0, fmaxf(cs[nt][0], cs[nt][1]));
            mx1 = fmaxf(mx1, fmaxf(cs[nt][2], cs[nt][3]));
        }
        mx0 = fmaxf(mx0, __shfl_xor_sync(0xffffffffu, mx0, 1));
        mx0 = fmaxf(mx0, __shfl_xor_sync(0xffffffffu, mx0, 2));
        mx1 = fmaxf(mx1, __shfl_xor_sync(0xffffffffu, mx1, 1));
        mx1 = fmaxf(mx1, __shfl_xor_sync(0xffffffffu, mx1, 2));

        const float mn0 = fmaxf(mr0, mx0);
        const float mn1 = fmaxf(mr1, mx1);
        const float corr0 = fast_exp2((mr0 - mn0) * LOG2E);
        const float corr1 = fast_exp2((mr1 - mn1) * LOG2E);
        mr0 = mn0; mr1 = mn1;

        float rs0 = 0.f, rs1 = 0.f;
#pragma unroll
        for (int nt = 0; nt < 8; ++nt) {
            float p0 = fast_exp2((cs[nt][0] - mn0) * LOG2E);
            float p1 = fast_exp2((cs[nt][1] - mn0) * LOG2E);
            float p2 = fast_exp2((cs[nt][2] - mn1) * LOG2E);
            float p3 = fast_exp2((cs[nt][3] - mn1) * LOG2E);
            cs[nt][0] = p0; cs[nt][1] = p1; cs[nt][2] = p2; cs[nt][3] = p3;
            rs0 += p0 + p1; rs1 += p2 + p3;
        }
        rs0 += __shfl_xor_sync(0xffffffffu, rs0, 1);
        rs0 += __shfl_xor_sync(0xffffffffu, rs0, 2);
        rs1 += __shfl_xor_sync(0xffffffffu, rs1, 1);
        rs1 += __shfl_xor_sync(0xffffffffu, rs1, 2);
        lr0 = lr0 * corr0 + rs0;
        lr1 = lr1 * corr1 + rs1;
#pragma unroll
        for (int t = 0; t < 16; ++t) {
            co[t][0] *= corr0; co[t][1] *= corr0;
            co[t][2] *= corr1; co[t][3] *= corr1;
        }

        uint32_t pa[4][4];
#pragma unroll
        for (int t = 0; t < 4; ++t) {
            PACK_F16(pa[t][0], cs[2 * t][1],     cs[2 * t][0]);
            PACK_F16(pa[t][1], cs[2 * t][3],     cs[2 * t][2]);
            PACK_F16(pa[t][2], cs[2 * t + 1][1], cs[2 * t + 1][0]);
            PACK_F16(pa[t][3], cs[2 * t + 1][3], cs[2 * t + 1][2]);
        }

#pragma unroll
        for (int ks = 0; ks < 4; ++ks) {
            const uint32_t voff = (uint32_t)(b_nrow * VSTR + ((ks << 4) + b_kcol) * 2);
#pragma unroll
            for (int nq = 0; nq < 8; ++nq) {
                uint32_t vhf[4];
                const uint32_t no = (uint32_t)(nq * 16 * VSTR);
                LDSM4(vhf, sV + no + voff);
                MMA_F16(co[nq * 2],     pa[ks], vhf[0], vhf[2]);
                MMA_F16(co[nq * 2 + 1], pa[ks], vhf[1], vhf[3]);
            }
        }
        __syncthreads();   // stage (jt&1) free for prefetch at jt+1
    }

    // ---- epilogue: normalize, split to bf16 hi/lo ----
    const float inv0 = 1.f / lr0;
    const float inv1 = 1.f / lr1;
    const size_t row0 = (size_t)(b * SEQ + q0 + m0 + (lane >> 2));
#pragma unroll
    for (int t = 0; t < 16; ++t) {
        const int col = h * HEAD_DIM + t * 8 + ((lane & 3) << 1);
        float a0 = co[t][0] * inv0, a1 = co[t][1] * inv0;
        float b0v = co[t][2] * inv1, b1v = co[t][3] * inv1;
        uint32_t h0 = __byte_perm(__float_as_uint(a0), __float_as_uint(a1), 0x7632);
        uint32_t h1 = __byte_perm(__float_as_uint(b0v), __float_as_uint(b1v), 0x7632);
        float l0a = a0 - __uint_as_float(__float_as_uint(a0) & 0xffff0000u);
        float l1a = a1 - __uint_as_float(__float_as_uint(a1) & 0xffff0000u);
        float l0b = b0v - __uint_as_float(__float_as_uint(b0v) & 0xffff0000u);
        float l1b = b1v - __uint_as_float(__float_as_uint(b1v) & 0xffff0000u);
        uint32_t lo0, lo1;
        CVT_BF2(lo0, l1a, l0a);
        CVT_BF2(lo1, l1b, l0b);
        *(uint32_t*)&oh[row0 * HIDDEN + col]       = h0;
        *(uint32_t*)&ol[row0 * HIDDEN + col]       = lo0;
        *(uint32_t*)&oh[(row0 + 8) * HIDDEN + col] = h1;
        *(uint32_t*)&ol[(row0 + 8) * HIDDEN + col] = lo1;
    }
}

// ---------------------------------------------------------------------------
// Launch
// ---------------------------------------------------------------------------
extern "C" void kernel_launch(void* const* d_in, const int* in_sizes, int n_in,
                              void* d_out, int out_size)
{
    const float* hidden  = (const float*)d_in[0];
    const float* w_qkv   = (const float*)d_in[1];
    const float* b_qkv   = (const float*)d_in[2];
    const float* w_dense = (const float*)d_in[3];
    const float* b_dense = (const float*)d_in[4];
    float* out = (float*)d_out;

    float* qkv_p;
    __nv_bfloat16 *hh, *hl, *wqh, *wql, *wdh, *wdl, *ath, *atl;
    __nv_bfloat16 *qh_p, *ql_p, *kh_p, *kl_p;
    __half *vh_p;
    cudaGetSymbolAddress((void**)&qkv_p, g_qkv);
    cudaGetSymbolAddress((void**)&hh,  g_hh);
    cudaGetSymbolAddress((void**)&hl,  g_hl);
    cudaGetSymbolAddress((void**)&wqh, g_wqh);
    cudaGetSymbolAddress((void**)&wql, g_wql);
    cudaGetSymbolAddress((void**)&wdh, g_wdh);
    cudaGetSymbolAddress((void**)&wdl, g_wdl);
    cudaGetSymbolAddress((void**)&ath, g_ath);
    cudaGetSymbolAddress((void**)&atl, g_atl);
    cudaGetSymbolAddress((void**)&qh_p, g_qh);
    cudaGetSymbolAddress((void**)&ql_p, g_ql);
    cudaGetSymbolAddress((void**)&kh_p, g_kh);
    cudaGetSymbolAddress((void**)&kl_p, g_kl);
    cudaGetSymbolAddress((void**)&vh_p, g_vh);

    cudaFuncSetAttribute(gemm_bf16p,
                         cudaFuncAttributeMaxDynamicSharedMemorySize, GSMEM);
    cudaFuncSetAttribute(attn_mma,
                         cudaFuncAttributeMaxDynamicSharedMemorySize, ATTN_SMEM);

    dim3 blk(256);

    // 0) pre-split GEMM operands
    {
        int n4 = TOKENS * HIDDEN / 4;
        split_f32<<<(n4 + 255) / 256, blk>>>((const float4*)hidden,
                                             (uint2*)hh, (uint2*)hl, n4);
        n4 = QKV_N * HIDDEN / 4;
        split_f32<<<(n4 + 255) / 256, blk>>>((const float4*)w_qkv,
                                             (uint2*)wqh, (uint2*)wql, n4);
        n4 = HIDDEN * HIDDEN / 4;
        split_f32<<<(n4 + 255) / 256, blk>>>((const float4*)w_dense,
                                             (uint2*)wdh, (uint2*)wdl, n4);
    }

    // 1) QKV projection
    gemm_bf16p<<<dim3(QKV_N / 128, TOKENS / 128), blk, GSMEM>>>(
        hh, hl, wqh, wql, b_qkv, qkv_p, TOKENS, QKV_N, HIDDEN);

    // 2) Convert Q (scaled), K to bf16 hi/lo
    convert_qk<<<(BH * SEQ) / 8, blk>>>(qkv_p, qh_p, ql_p, kh_p, kl_p);

    // 3) Convert + transpose V to fp16 (hi only)
    convert_v<<<dim3(SEQ / 32, HEAD_DIM / 32, BH), blk>>>(qkv_p, vh_p);

    // 4) Tensor-core flash attention (Q in registers, bf16 hi/lo out)
    attn_mma<<<dim3(SEQ / 128, BH), blk, ATTN_SMEM>>>(
        qh_p, ql_p, kh_p, kl_p, vh_p, ath, atl);

    // 5) Dense projection
    gemm_bf16p<<<dim3(HIDDEN / 128, TOKENS / 128), blk, GSMEM>>>(
        ath, atl, wdh, wdl, b_dense, out, TOKENS, HIDDEN, HIDDEN);
}

// round 15
// speedup vs baseline: 1.1025x; 1.0204x over previous
#include <cuda_runtime.h>
#include <cuda_bf16.h>
#include <cuda_fp16.h>
#include <cstdint>

#define HIDDEN   2048
#define NHEADS   16
#define HEAD_DIM 128
#define BATCH    4
#define SEQ      2048
#define TOKENS   (BATCH * SEQ)     /* 8192 */
#define QKV_N    (3 * HIDDEN)      /* 6144 */
#define BH       (BATCH * NHEADS)  /* 64   */
#define SOFTMAX_SCALE 0.08838834764831845f
#define LOG2E 1.4426950408889634f

// ---------------------------------------------------------------------------
// Scratch (device globals)
// ---------------------------------------------------------------------------
__device__ __nv_bfloat16 g_hh [(size_t)TOKENS * HIDDEN];
__device__ __nv_bfloat16 g_hl [(size_t)TOKENS * HIDDEN];
__device__ __nv_bfloat16 g_wqh[(size_t)QKV_N * HIDDEN];
__device__ __nv_bfloat16 g_wql[(size_t)QKV_N * HIDDEN];
__device__ __nv_bfloat16 g_wdh[(size_t)HIDDEN * HIDDEN];
__device__ __nv_bfloat16 g_wdl[(size_t)HIDDEN * HIDDEN];
__device__ __nv_bfloat16 g_ath[(size_t)TOKENS * HIDDEN];
__device__ __nv_bfloat16 g_atl[(size_t)TOKENS * HIDDEN];
__device__ __nv_bfloat16 g_qh[(size_t)BH * SEQ * HEAD_DIM];
__device__ __nv_bfloat16 g_ql[(size_t)BH * SEQ * HEAD_DIM];
__device__ __nv_bfloat16 g_kh[(size_t)BH * SEQ * HEAD_DIM];
__device__ __nv_bfloat16 g_kl[(size_t)BH * SEQ * HEAD_DIM];
__device__ __half g_vh[(size_t)BH * HEAD_DIM * SEQ];       // [bh][d][s]

// ---------------------------------------------------------------------------
// helpers
// ---------------------------------------------------------------------------
__device__ __forceinline__ uint32_t smem_u32(const void* p) {
    uint32_t a;
    asm("{ .reg .u64 t; cvta.to.shared.u64 t, %1; cvt.u32.u64 %0, t; }"
        : "=r"(a) : "l"(p));
    return a;
}
#define CVT_BF2(d, up, lo) \
    asm("cvt.rn.bf16x2.f32 %0, %1, %2;" : "=r"(d) : "f"(up), "f"(lo))
#define PACK_F16(d, up, lo) \
    asm("cvt.rn.f16x2.f32 %0, %1, %2;" : "=r"(d) : "f"(up), "f"(lo))

__device__ __forceinline__ float fast_exp2(float x) {
    float y;
    asm("ex2.approx.ftz.f32 %0, %1;" : "=f"(y) : "f"(x));
    return y;
}

#define LDSM4(r, addr) \
    asm volatile("ldmatrix.sync.aligned.m8n8.x4.shared.b16 {%0,%1,%2,%3}, [%4];" \
        : "=r"((r)[0]), "=r"((r)[1]), "=r"((r)[2]), "=r"((r)[3]) : "r"(addr))

#define MMA_BF16(cr, a, b0, b1) \
    asm volatile("mma.sync.aligned.m16n8k16.row.col.f32.bf16.bf16.f32 " \
        "{%0,%1,%2,%3}, {%4,%5,%6,%7}, {%8,%9}, {%0,%1,%2,%3};" \
        : "+f"((cr)[0]), "+f"((cr)[1]), "+f"((cr)[2]), "+f"((cr)[3]) \
        : "r"((a)[0]), "r"((a)[1]), "r"((a)[2]), "r"((a)[3]), "r"(b0), "r"(b1))

#define MMA_F16(cr, a, b0, b1) \
    asm volatile("mma.sync.aligned.m16n8k16.row.col.f32.f16.f16.f32 " \
        "{%0,%1,%2,%3}, {%4,%5,%6,%7}, {%8,%9}, {%0,%1,%2,%3};" \
        : "+f"((cr)[0]), "+f"((cr)[1]), "+f"((cr)[2]), "+f"((cr)[3]) \
        : "r"((a)[0]), "r"((a)[1]), "r"((a)[2]), "r"((a)[3]), "r"(b0), "r"(b1))

#define CP16(dst, src) \
    asm volatile("cp.async.ca.shared.global [%0], [%1], 16;" \
                 :: "r"(dst), "l"(src) : "memory")
#define CP_COMMIT() asm volatile("cp.async.commit_group;" ::: "memory")
#define CP_WAIT(n)  asm volatile("cp.async.wait_group %0;" :: "n"(n) : "memory")

// ---------------------------------------------------------------------------
// Elementwise fp32 -> bf16 hi/lo split
// ---------------------------------------------------------------------------
__global__ void __launch_bounds__(256) split_f32(
    const float4* __restrict__ src, uint2* __restrict__ hi,
    uint2* __restrict__ lo, int n4)
{
    int i = blockIdx.x * 256 + threadIdx.x;
    if (i >= n4) return;
    float4 v = src[i];
    uint32_t h0 = __byte_perm(__float_as_uint(v.x), __float_as_uint(v.y), 0x7632);
    uint32_t h1 = __byte_perm(__float_as_uint(v.z), __float_as_uint(v.w), 0x7632);
    float lx = v.x - __uint_as_float(__float_as_uint(v.x) & 0xffff0000u);
    float ly = v.y - __uint_as_float(__float_as_uint(v.y) & 0xffff0000u);
    float lz = v.z - __uint_as_float(__float_as_uint(v.z) & 0xffff0000u);
    float lw = v.w - __uint_as_float(__float_as_uint(v.w) & 0xffff0000u);
    uint32_t l0, l1;
    CVT_BF2(l0, ly, lx);
    CVT_BF2(l1, lw, lz);
    hi[i] = make_uint2(h0, h1);
    lo[i] = make_uint2(l0, l1);
}

// ---------------------------------------------------------------------------
// Pre-split bf16x3 NT GEMM via mma.sync + cp.async (R12 mainloop, 2-stage).
// MODE 0: C = fp32 + bias (dense).
// MODE 1: QKV fused epilogue through smem staging -> coalesced writes:
//         Q (scaled) bf16 hi/lo [bh][s][d]; K bf16 hi/lo [bh][s][d];
//         V fp16 TRANSPOSED [bh][d][s].
// ---------------------------------------------------------------------------
#define GROWB   80
#define GMAT    (128 * GROWB)
#define GSTAGE  (4 * GMAT)
#define GSMEM   (2 * GSTAGE)               /* 81920 */
#define EPL_STR 272                        /* staging row stride */

template<int MODE>
__global__ void __launch_bounds__(256, 1) gemm_bf16p(
    const __nv_bfloat16* __restrict__ Ah, const __nv_bfloat16* __restrict__ Al,
    const __nv_bfloat16* __restrict__ Bh, const __nv_bfloat16* __restrict__ Bl,
    const float* __restrict__ bias, float* __restrict__ C,
    __nv_bfloat16* __restrict__ qh, __nv_bfloat16* __restrict__ ql,
    __nv_bfloat16* __restrict__ kh, __nv_bfloat16* __restrict__ kl,
    __half* __restrict__ vh,
    int M, int N, int K)
{
    extern __shared__ char smem[];
    const uint32_t sbase = smem_u32(smem);

    const int tid  = threadIdx.x;
    const int wid  = tid >> 5;
    const int lane = tid & 31;
    const int bm = blockIdx.y << 7;
    const int bn = blockIdx.x << 7;

    const int m0 = (wid & 3) << 5;
    const int n0 = (wid >> 2) << 6;

    float c[2][8][4];
#pragma unroll
    for (int mt = 0; mt < 2; ++mt)
#pragma unroll
        for (int nt = 0; nt < 8; ++nt)
#pragma unroll
            for (int q = 0; q < 4; ++q) c[mt][nt][q] = 0.f;

    const int a_row = lane & 15;
    const int a_col = ((lane >> 4) & 1) << 3;
    const int b_mat = lane >> 3;
    const int b_nrow = (lane & 7) + ((b_mat & 1) << 3);
    const int b_kcol = (b_mat >> 1) << 3;

    const int lrow = tid >> 1;
    const int lseg = (tid & 1) << 1;
    const __nv_bfloat16* Ahg = Ah + (size_t)(bm + lrow) * K + lseg * 8;
    const __nv_bfloat16* Alg = Al + (size_t)(bm + lrow) * K + lseg * 8;
    const __nv_bfloat16* Bhg = Bh + (size_t)(bn + lrow) * K + lseg * 8;
    const __nv_bfloat16* Blg = Bl + (size_t)(bn + lrow) * K + lseg * 8;
    const uint32_t sto = (uint32_t)(lrow * GROWB + lseg * 16);

    const int KT = K >> 5;

    {
        const uint32_t s0 = sbase + sto;
        CP16(s0,             Ahg);      CP16(s0 + 16,             Ahg + 8);
        CP16(s0 + GMAT,      Alg);      CP16(s0 + GMAT + 16,      Alg + 8);
        CP16(s0 + 2 * GMAT,  Bhg);      CP16(s0 + 2 * GMAT + 16,  Bhg + 8);
        CP16(s0 + 3 * GMAT,  Blg);      CP16(s0 + 3 * GMAT + 16,  Blg + 8);
        CP_COMMIT();
    }

    for (int it = 0; it < KT; ++it) {
        const int buf = it & 1;
        if (it + 1 < KT) {
            const uint32_t s1 = sbase + ((it + 1) & 1) * GSTAGE + sto;
            const size_t go = (size_t)(it + 1) * 32;
            CP16(s1,            Ahg + go);  CP16(s1 + 16,            Ahg + go + 8);
            CP16(s1 + GMAT,     Alg + go);  CP16(s1 + GMAT + 16,     Alg + go + 8);
            CP16(s1 + 2 * GMAT, Bhg + go);  CP16(s1 + 2 * GMAT + 16, Bhg + go + 8);
            CP16(s1 + 3 * GMAT, Blg + go);  CP16(s1 + 3 * GMAT + 16, Blg + go + 8);
            CP_COMMIT();
            CP_WAIT(1);
        } else {
            CP_WAIT(0);
        }
        __syncthreads();

        const uint32_t sA  = sbase + buf * GSTAGE;
        const uint32_t sAl = sA + GMAT;
        const uint32_t sB  = sA + 2 * GMAT;
        const uint32_t sBl = sA + 3 * GMAT;

#pragma unroll
        for (int ks = 0; ks < 2; ++ks) {
            const int kb = ks << 4;
            uint32_t ah[2][4], al[2][4], bh[4][4], bl[4][4];
            const uint32_t aoff = (uint32_t)(a_row * GROWB + (kb + a_col) * 2);
            const uint32_t boff = (uint32_t)(b_nrow * GROWB + (kb + b_kcol) * 2);
#pragma unroll
            for (int mt = 0; mt < 2; ++mt) {
                const uint32_t mo = (uint32_t)((m0 + mt * 16) * GROWB);
                LDSM4(ah[mt], sA  + mo + aoff);
                LDSM4(al[mt], sAl + mo + aoff);
            }
#pragma unroll
            for (int nq = 0; nq < 4; ++nq) {
                const uint32_t no = (uint32_t)((n0 + nq * 16) * GROWB);
                LDSM4(bh[nq], sB  + no + boff);
                LDSM4(bl[nq], sBl + no + boff);
            }
#pragma unroll
            for (int mt = 0; mt < 2; ++mt)
#pragma unroll
                for (int nt = 0; nt < 8; ++nt) {
                    const int nq = nt >> 1, sel = nt & 1;
                    MMA_BF16(c[mt][nt], ah[mt], bh[nq][sel], bh[nq][sel + 2]);
                    MMA_BF16(c[mt][nt], ah[mt], bl[nq][sel], bl[nq][sel + 2]);
                    MMA_BF16(c[mt][nt], al[mt], bh[nq][sel], bh[nq][sel + 2]);
                }
        }
        __syncthreads();
    }

    const int grp = lane >> 2, tig = lane & 3;

    if (MODE == 0) {
#pragma unroll
        for (int nt = 0; nt < 8; ++nt) {
            const int col = bn + n0 + nt * 8 + tig * 2;
            const float2 bv = *(const float2*)&bias[col];
#pragma unroll
            for (int mt = 0; mt < 2; ++mt) {
                const int row = bm + m0 + mt * 16 + grp;
                float2 v0 = make_float2(c[mt][nt][0] + bv.x, c[mt][nt][1] + bv.y);
                float2 v1 = make_float2(c[mt][nt][2] + bv.x, c[mt][nt][3] + bv.y);
                *(float2*)&C[(size_t)row * N + col]       = v0;
                *(float2*)&C[(size_t)(row + 8) * N + col] = v1;
            }
        }
    } else {
        // ---- fused QKV epilogue: stage in smem, coalesced plane writes ----
        const int typ = bn >> 11;             // 0=Q 1=K 2=V
        const int h   = (bn & 2047) >> 7;
        const int bb  = bm >> 11;             // batch index
        const int s0g = bm & 2047;            // seq offset of tile
        char* p0 = smem;                      // hi plane (or V^T fp16)
        char* p1 = smem + 128 * EPL_STR;      // lo plane

#pragma unroll
        for (int nt = 0; nt < 8; ++nt) {
            const int col = n0 + nt * 8 + tig * 2;   // d within head (even)
            const float2 bv = *(const float2*)&bias[bn + col];
#pragma unroll
            for (int mt = 0; mt < 2; ++mt) {
#pragma unroll
                for (int half = 0; half < 2; ++half) {
                    const int row = m0 + mt * 16 + grp + half * 8;   // s_local
                    float v0 = c[mt][nt][half * 2 + 0] + bv.x;
                    float v1 = c[mt][nt][half * 2 + 1] + bv.y;
                    if (typ == 0) { v0 *= SOFTMAX_SCALE; v1 *= SOFTMAX_SCALE; }
                    if (typ == 2) {
                        // V: stage TRANSPOSED [d][s_local] fp16
                        *(__half*)(p0 + col * EPL_STR + row * 2) =
                            __float2half_rn(v0);
                        *(__half*)(p0 + (col + 1) * EPL_STR + row * 2) =
                            __float2half_rn(v1);
                    } else {
                        uint32_t hi = __byte_perm(__float_as_uint(v0),
                                                  __float_as_uint(v1), 0x7632);
                        float l0 = v0 - __uint_as_float(__float_as_uint(v0) & 0xffff0000u);
                        float l1 = v1 - __uint_as_float(__float_as_uint(v1) & 0xffff0000u);
                        uint32_t lo;
                        CVT_BF2(lo, l1, l0);
                        *(uint32_t*)(p0 + row * EPL_STR + col * 2) = hi;
                        *(uint32_t*)(p1 + row * EPL_STR + col * 2) = lo;
                    }
                }
            }
        }
        __syncthreads();

        if (typ <= 1) {
            __nv_bfloat16* dh = (typ == 0) ? qh : kh;
            __nv_bfloat16* dl = (typ == 0) ? ql : kl;
            const size_t base = ((size_t)(bb * 16 + h) * SEQ + s0g) * HEAD_DIM;
#pragma unroll
            for (int p = 0; p < 8; ++p) {
                const int i = tid + (p << 8);
                const int row = i >> 4, seg = i & 15;
                *(uint4*)(dh + base + (size_t)row * HEAD_DIM + seg * 8) =
                    *(const uint4*)(p0 + row * EPL_STR + seg * 16);
                *(uint4*)(dl + base + (size_t)row * HEAD_DIM + seg * 8) =
                    *(const uint4*)(p1 + row * EPL_STR + seg * 16);
            }
        } else {
            const size_t vb = (size_t)(bb * 16 + h) * HEAD_DIM * SEQ + s0g;
#pragma unroll
            for (int p = 0; p < 8; ++p) {
                const int i = tid + (p << 8);
                const int d = i >> 4, seg = i & 15;
                *(uint4*)(vh + vb + (size_t)d * SEQ + seg * 8) =
                    *(const uint4*)(p0 + d * EPL_STR + seg * 16);
            }
        }
    }
}

// ---------------------------------------------------------------------------
// Flash attention (exact R14): Q register-resident, K/V cp.async double buffer.
// q-tile 128, key-tile 64, 8 warps. S: bf16x3. PV: fp16 hi.
// ---------------------------------------------------------------------------
#define QSTR 272
#define VSTR 144
#define AKL  (64 * QSTR)                  /* 17408 */
#define AVH  (2 * 64 * QSTR)              /* 34816 */
#define ASTAGE (2 * 64 * QSTR + 128 * VSTR)   /* 53248 */
#define ATTN_SMEM (2 * ASTAGE)            /* 106496 */

__global__ void __launch_bounds__(256, 1) attn_mma(
    const __nv_bfloat16* __restrict__ qh, const __nv_bfloat16* __restrict__ ql,
    const __nv_bfloat16* __restrict__ kh, const __nv_bfloat16* __restrict__ kl,
    const __half* __restrict__ vh,
    __nv_bfloat16* __restrict__ oh, __nv_bfloat16* __restrict__ ol)
{
    extern __shared__ char sm[];
    const uint32_t sbase = smem_u32(sm);

    const int iq = (int)gridDim.x - 1 - (int)blockIdx.x;   // heavy tiles first
    const int bh = blockIdx.y;
    const int b  = bh >> 4;
    const int h  = bh & 15;
    const int tid  = threadIdx.x;
    const int wid  = tid >> 5;
    const int lane = tid & 31;
    const int q0 = iq << 7;
    const int m0 = wid << 4;

    const int nkt = 2 * (iq + 1);

    const int a_row = lane & 15;
    const int a_col = ((lane >> 4) & 1) << 3;
    const int b_mat = lane >> 3;
    const int b_nrow = (lane & 7) + ((b_mat & 1) << 3);
    const int b_kcol = (b_mat >> 1) << 3;

    // ---- stage Q in smem once, ldmatrix to persistent registers ----
    uint32_t qfh[8][4], qfl[8][4];
    {
        const uint4* qhg = (const uint4*)(qh + ((size_t)bh * SEQ + q0) * HEAD_DIM);
        const uint4* qlg = (const uint4*)(ql + ((size_t)bh * SEQ + q0) * HEAD_DIM);
#pragma unroll
        for (int i = tid; i < 2048; i += 256) {
            const int row = i >> 4, seg = i & 15;
            *(uint4*)(sm + row * QSTR + seg * 16)         = qhg[row * 16 + seg];
            *(uint4*)(sm + 34816 + row * QSTR + seg * 16) = qlg[row * 16 + seg];
        }
        __syncthreads();
#pragma unroll
        for (int ks = 0; ks < 8; ++ks) {
            const uint32_t aoff =
                (uint32_t)((m0 + a_row) * QSTR + ((ks << 4) + a_col) * 2);
            LDSM4(qfh[ks], sbase + aoff);
            LDSM4(qfl[ks], sbase + 34816 + aoff);
        }
        __syncthreads();   // Q fully consumed; smem now free for K/V stages
    }

    // stage loader: key-tile jt -> stage stg (cp.async)
    auto load_stage = [&](int jt, int stg) {
        const int kt0 = jt << 6;
        const __nv_bfloat16* khg = kh + ((size_t)bh * SEQ + kt0) * HEAD_DIM;
        const __nv_bfloat16* klg = kl + ((size_t)bh * SEQ + kt0) * HEAD_DIM;
        const uint32_t sb = sbase + stg * ASTAGE;
#pragma unroll
        for (int p = 0; p < 4; ++p) {
            const int i = tid + (p << 8);
            const int row = i >> 4, seg = i & 15;
            const uint32_t dst = sb + row * QSTR + seg * 16;
            CP16(dst,       khg + row * HEAD_DIM + seg * 8);
            CP16(dst + AKL, klg + row * HEAD_DIM + seg * 8);
        }
#pragma unroll
        for (int p = 0; p < 4; ++p) {
            const int i = tid + (p << 8);
            const int d = i >> 3, seg = i & 7;
            CP16(sb + AVH + d * VSTR + seg * 16,
                 vh + ((size_t)bh * HEAD_DIM + d) * SEQ + kt0 + seg * 8);
        }
        CP_COMMIT();
    };

    load_stage(0, 0);

    float co[16][4];
#pragma unroll
    for (int t = 0; t < 16; ++t)
#pragma unroll
        for (int q = 0; q < 4; ++q) co[t][q] = 0.f;
    float mr0 = -1e30f, mr1 = -1e30f, lr0 = 0.f, lr1 = 0.f;

    for (int jt = 0; jt < nkt; ++jt) {
        if (jt + 1 < nkt) {
            load_stage(jt + 1, (jt + 1) & 1);
            CP_WAIT(1);
        } else {
            CP_WAIT(0);
        }
        __syncthreads();

        const uint32_t sS = sbase + (jt & 1) * ASTAGE;
        const uint32_t sK  = sS;
        const uint32_t sKl = sS + AKL;
        const uint32_t sV  = sS + AVH;
        const int kt0 = jt << 6;

        float cs[8][4];
#pragma unroll
        for (int t = 0; t < 8; ++t)
#pragma unroll
            for (int q = 0; q < 4; ++q) cs[t][q] = 0.f;

#pragma unroll
        for (int ks = 0; ks < 8; ++ks) {
            const int kb = ks << 4;
            uint32_t bhf[4][4], blf[4][4];
            const uint32_t boff = (uint32_t)(b_nrow * QSTR + (kb + b_kcol) * 2);
#pragma unroll
            for (int nq = 0; nq < 4; ++nq) {
                const uint32_t no = (uint32_t)(nq * 16 * QSTR);
                LDSM4(bhf[nq], sK  + no + boff);
                LDSM4(blf[nq], sKl + no + boff);
            }
#pragma unroll
            for (int nt = 0; nt < 8; ++nt) {
                const int nq = nt >> 1, sel = nt & 1;
                MMA_BF16(cs[nt], qfh[ks], bhf[nq][sel], bhf[nq][sel + 2]);
                MMA_BF16(cs[nt], qfh[ks], blf[nq][sel], blf[nq][sel + 2]);
                MMA_BF16(cs[nt], qfl[ks], bhf[nq][sel], bhf[nq][sel + 2]);
            }
        }

        if (jt >= 2 * iq) {
            const int rg0 = q0 + m0 + (lane >> 2);
            const int rg1 = rg0 + 8;
            const int cb  = kt0 + ((lane & 3) << 1);
#pragma unroll
            for (int nt = 0; nt < 8; ++nt) {
                const int c0 = cb + nt * 8;
                if (c0     > rg0) cs[nt][0] = -1e30f;
                if (c0 + 1 > rg0) cs[nt][1] = -1e30f;
                if (c0     > rg1) cs[nt][2] = -1e30f;
                if (c0 + 1 > rg1) cs[nt][3] = -1e30f;
            }
        }

        float mx0 = cs[0][0], mx1 = cs[0][2];
#pragma unroll
        for (int nt = 0; nt < 8; ++nt) {
            mx0 = fmaxf(mx0, fmaxf(cs[nt][0], cs[nt][1]));
            mx1 = fmaxf(mx1, fmaxf(cs[nt][2], cs[nt][3]));
        }
        mx0 = fmaxf(mx0, __shfl_xor_sync(0xffffffffu, mx0, 1));
        mx0 = fmaxf(mx0, __shfl_xor_sync(0xffffffffu, mx0, 2));
        mx1 = fmaxf(mx1, __shfl_xor_sync(0xffffffffu, mx1, 1));
        mx1 = fmaxf(mx1, __shfl_xor_sync(0xffffffffu, mx1, 2));

        const float mn0 = fmaxf(mr0, mx0);
        const float mn1 = fmaxf(mr1, mx1);
        const float corr0 = fast_exp2((mr0 - mn0) * LOG2E);
        const float corr1 = fast_exp2((mr1 - mn1) * LOG2E);
        mr0 = mn0; mr1 = mn1;

        float rs0 = 0.f, rs1 = 0.f;
#pragma unroll
        for (int nt = 0; nt < 8; ++nt) {
            float p0 = fast_exp2((cs[nt][0] - mn0) * LOG2E);
            float p1 = fast_exp2((cs[nt][1] - mn0) * LOG2E);
            float p2 = fast_exp2((cs[nt][2] - mn1) * LOG2E);
            float p3 = fast_exp2((cs[nt][3] - mn1) * LOG2E);
            cs[nt][0] = p0; cs[nt][1] = p1; cs[nt][2] = p2; cs[nt][3] = p3;
            rs0 += p0 + p1; rs1 += p2 + p3;
        }
        rs0 += __shfl_xor_sync(0xffffffffu, rs0, 1);
        rs0 += __shfl_xor_sync(0xffffffffu, rs0, 2);
        rs1 += __shfl_xor_sync(0xffffffffu, rs1, 1);
        rs1 += __shfl_xor_sync(0xffffffffu, rs1, 2);
        lr0 = lr0 * corr0 + rs0;
        lr1 = lr1 * corr1 + rs1;
#pragma unroll
        for (int t = 0; t < 16; ++t) {
            co[t][0] *= corr0; co[t][1] *= corr0;
            co[t][2] *= corr1; co[t][3] *= corr1;
        }

        uint32_t pa[4][4];
#pragma unroll
        for (int t = 0; t < 4; ++t) {
            PACK_F16(pa[t][0], cs[2 * t][1],     cs[2 * t][0]);
            PACK_F16(pa[t][1], cs[2 * t][3],     cs[2 * t][2]);
            PACK_F16(pa[t][2], cs[2 * t + 1][1], cs[2 * t + 1][0]);
            PACK_F16(pa[t][3], cs[2 * t + 1][3], cs[2 * t + 1][2]);
        }

#pragma unroll
        for (int ks = 0; ks < 4; ++ks) {
            const uint32_t voff = (uint32_t)(b_nrow * VSTR + ((ks << 4) + b_kcol) * 2);
#pragma unroll
            for (int nq = 0; nq < 8; ++nq) {
                uint32_t vhf[4];
                const uint32_t no = (uint32_t)(nq * 16 * VSTR);
                LDSM4(vhf, sV + no + voff);
                MMA_F16(co[nq * 2],     pa[ks], vhf[0], vhf[2]);
                MMA_F16(co[nq * 2 + 1], pa[ks], vhf[1], vhf[3]);
            }
        }
        __syncthreads();
    }

    // ---- epilogue: normalize, split to bf16 hi/lo ----
    const float inv0 = 1.f / lr0;
    const float inv1 = 1.f / lr1;
    const size_t row0 = (size_t)(b * SEQ + q0 + m0 + (lane >> 2));
#pragma unroll
    for (int t = 0; t < 16; ++t) {
        const int col = h * HEAD_DIM + t * 8 + ((lane & 3) << 1);
        float a0 = co[t][0] * inv0, a1 = co[t][1] * inv0;
        float b0v = co[t][2] * inv1, b1v = co[t][3] * inv1;
        uint32_t h0 = __byte_perm(__float_as_uint(a0), __float_as_uint(a1), 0x7632);
        uint32_t h1 = __byte_perm(__float_as_uint(b0v), __float_as_uint(b1v), 0x7632);
        float l0a = a0 - __uint_as_float(__float_as_uint(a0) & 0xffff0000u);
        float l1a = a1 - __uint_as_float(__float_as_uint(a1) & 0xffff0000u);
        float l0b = b0v - __uint_as_float(__float_as_uint(b0v) & 0xffff0000u);
        float l1b = b1v - __uint_as_float(__float_as_uint(b1v) & 0xffff0000u);
        uint32_t lo0, lo1;
        CVT_BF2(lo0, l1a, l0a);
        CVT_BF2(lo1, l1b, l0b);
        *(uint32_t*)&oh[row0 * HIDDEN + col]       = h0;
        *(uint32_t*)&ol[row0 * HIDDEN + col]       = lo0;
        *(uint32_t*)&oh[(row0 + 8) * HIDDEN + col] = h1;
        *(uint32_t*)&ol[(row0 + 8) * HIDDEN + col] = lo1;
    }
}

// ---------------------------------------------------------------------------
// Launch
// ---------------------------------------------------------------------------
extern "C" void kernel_launch(void* const* d_in, const int* in_sizes, int n_in,
                              void* d_out, int out_size)
{
    const float* hidden  = (const float*)d_in[0];
    const float* w_qkv   = (const float*)d_in[1];
    const float* b_qkv   = (const float*)d_in[2];
    const float* w_dense = (const float*)d_in[3];
    const float* b_dense = (const float*)d_in[4];
    float* out = (float*)d_out;

    __nv_bfloat16 *hh, *hl, *wqh, *wql, *wdh, *wdl, *ath, *atl;
    __nv_bfloat16 *qh_p, *ql_p, *kh_p, *kl_p;
    __half *vh_p;
    cudaGetSymbolAddress((void**)&hh,  g_hh);
    cudaGetSymbolAddress((void**)&hl,  g_hl);
    cudaGetSymbolAddress((void**)&wqh, g_wqh);
    cudaGetSymbolAddress((void**)&wql, g_wql);
    cudaGetSymbolAddress((void**)&wdh, g_wdh);
    cudaGetSymbolAddress((void**)&wdl, g_wdl);
    cudaGetSymbolAddress((void**)&ath, g_ath);
    cudaGetSymbolAddress((void**)&atl, g_atl);
    cudaGetSymbolAddress((void**)&qh_p, g_qh);
    cudaGetSymbolAddress((void**)&ql_p, g_ql);
    cudaGetSymbolAddress((void**)&kh_p, g_kh);
    cudaGetSymbolAddress((void**)&kl_p, g_kl);
    cudaGetSymbolAddress((void**)&vh_p, g_vh);

    cudaFuncSetAttribute(gemm_bf16p<0>,
                         cudaFuncAttributeMaxDynamicSharedMemorySize, GSMEM);
    cudaFuncSetAttribute(gemm_bf16p<1>,
                         cudaFuncAttributeMaxDynamicSharedMemorySize, GSMEM);
    cudaFuncSetAttribute(attn_mma,
                         cudaFuncAttributeMaxDynamicSharedMemorySize, ATTN_SMEM);

    dim3 blk(256);

    // 0) pre-split GEMM operands
    {
        int n4 = TOKENS * HIDDEN / 4;
        split_f32<<<(n4 + 255) / 256, blk>>>((const float4*)hidden,
                                             (uint2*)hh, (uint2*)hl, n4);
        n4 = QKV_N * HIDDEN / 4;
        split_f32<<<(n4 + 255) / 256, blk>>>((const float4*)w_qkv,
                                             (uint2*)wqh, (uint2*)wql, n4);
        n4 = HIDDEN * HIDDEN / 4;
        split_f32<<<(n4 + 255) / 256, blk>>>((const float4*)w_dense,
                                             (uint2*)wdh, (uint2*)wdl, n4);
    }

    // 1) QKV projection with fused Q/K/V epilogue (smem-staged, coalesced)
    gemm_bf16p<1><<<dim3(QKV_N / 128, TOKENS / 128), blk, GSMEM>>>(
        hh, hl, wqh, wql, b_qkv, nullptr,
        qh_p, ql_p, kh_p, kl_p, vh_p, TOKENS, QKV_N, HIDDEN);

    // 2) Tensor-core flash attention (Q in registers, bf16 hi/lo out)
    attn_mma<<<dim3(SEQ / 128, BH), blk, ATTN_SMEM>>>(
        qh_p, ql_p, kh_p, kl_p, vh_p, ath, atl);

    // 3) Dense projection
    gemm_bf16p<0><<<dim3(HIDDEN / 128, TOKENS / 128), blk, GSMEM>>>(
        ath, atl, wdh, wdl, b_dense, out,
        nullptr, nullptr, nullptr, nullptr, nullptr, TOKENS, HIDDEN, HIDDEN);
}